// round 16
// baseline (speedup 1.0000x reference)
#include <cuda_runtime.h>
#include <cuda_bf16.h>
#include <cuda_fp16.h>
#include <math.h>

// ---------------- problem constants ----------------
#define N_SW   131
#define NLC    33                 // distinct |L-32| classes
#define NM     16                 // only m<16 nonzero
#define BATCH  128
#define NV1    49
#define ROWS   (BATCH*NLC*NM)     // 67584

// ---------------- GEMM formulation ----------------
// A[row][k] fp16 (persistent gmem, written by prev step's Phase C):
//   k<144 -> O_r (s=k), k in [144,288) -> O_i (s=k-144); padding k in [131,144)+[275,288) = 0
// S[k][t] fp16 (288 x 136): k<131 -> C_r[k][t]; 144<=k<275 -> -C_i[k-144][t]; else 0
// unit ntG in [0,34): G=ntG>=17 selects G_r/G_i, nt=ntG-17G selects n-tile.
// G_r uses S rows kt; G_i uses +-S rows kt+-9 (neg for kt<9). Single-pass fp16 MMA.
#define KHALF  144
#define KDIM   288
#define NDIM   136
#define SSTRIDE_B 272             // 17*16, ldsm-aligned
#define ASTRIDE_B 592             // 37*16, ldsm-aligned, conflict-free
#define AG_U4   36                // uint4 per A gmem row (576 B)
#define CHUNK  96
#define NCHUNK (ROWS/CHUNK)       // 704
#define GRID   148
#define TPB    768                // 24 warps: 3 m-groups x 8 n-groups
#define NUNIT  5                  // ntG = nw + 8*j, j<5 (skip ntG>33)

#define S_BYTES  (KDIM*NDIM*2)    // 78336
#define S_OFF    0
#define A_OFF    S_BYTES          // 78336
#define A_BYTES  (CHUNK*ASTRIDE_B)// 56832
#define G_OFF    (A_OFF + A_BYTES)
#define G_BYTES  (CHUNK*ASTRIDE_B)
#define SMEM_BYTES (G_OFF + G_BYTES)   // 192000
#define GSTR16   296              // fp16 units per G row (592B, conflict-free)

// ---------------- persistent device scratch ----------------
__device__ unsigned g_fh[(size_t)ROWS * N_SW];            // field as half2 (fr,fi)
__device__ __align__(16) __half g_A[(size_t)ROWS * KDIM]; // out (A operand), fp16
__device__ __align__(16) __half g_S[KDIM * NDIM];
__device__ float  g_gain[N_SW];
__device__ float  g_pinj[BATCH * NM * NV1];
__device__ float  g_erow[10 * ROWS];
__device__ int    g_absmax_bits;

// ---------------- helpers ----------------
__device__ __forceinline__ unsigned smem_addr(const void* p) {
    unsigned a;
    asm("{ .reg .u64 t; cvta.to.shared.u64 t, %1; cvt.u32.u64 %0, t; }" : "=r"(a) : "l"(p));
    return a;
}
#define LDSM4(R, addr) \
    asm volatile("ldmatrix.sync.aligned.m8n8.x4.shared.b16 {%0,%1,%2,%3}, [%4];" \
        : "=r"((R)[0]), "=r"((R)[1]), "=r"((R)[2]), "=r"((R)[3]) : "r"(addr))
#define LDSM2T(R, addr) \
    asm volatile("ldmatrix.sync.aligned.m8n8.x2.trans.shared.b16 {%0,%1}, [%2];" \
        : "=r"((R)[0]), "=r"((R)[1]) : "r"(addr))
#define MMA_F16(C, A, B) \
    asm volatile("mma.sync.aligned.m16n8k16.row.col.f32.f16.f16.f32 " \
        "{%0,%1,%2,%3}, {%4,%5,%6,%7}, {%8,%9}, {%0,%1,%2,%3};" \
        : "+f"((C)[0]), "+f"((C)[1]), "+f"((C)[2]), "+f"((C)[3]) \
        : "r"((A)[0]), "r"((A)[1]), "r"((A)[2]), "r"((A)[3]), "r"((B)[0]), "r"((B)[1]))

__device__ __forceinline__ float tanh_fast(float x) {
    float r;
    asm("tanh.approx.f32 %0, %1;" : "=f"(r) : "f"(x));
    return r;
}
__device__ __forceinline__ void outfun(float fr, float fi, float g,
                                       float& orr, float& oii) {
    float sq  = fmaf(fr, fr, fmaf(fi, fi, 1e-8f));
    float inv = rsqrtf(sq);
    float sc  = tanh_fast(g * sq * inv) * inv;
    orr = fr * sc;
    oii = fi * sc;
}
__device__ __forceinline__ unsigned pack_h2(float a, float b) {
    __half2 h = __floats2half2_rn(a, b);
    return *(unsigned*)&h;
}
__device__ __forceinline__ void unpack_h2(unsigned v, float& a, float& b) {
    __half2 h = *(__half2*)&v;
    float2 f = __half22float2(h);
    a = f.x; b = f.y;
}

// ---------------- prep kernels ----------------
__global__ void k_init() { if (threadIdx.x == 0) g_absmax_bits = 0; }

__global__ void k_absmax(const float* __restrict__ img, int n) {
    int i = blockIdx.x * blockDim.x + threadIdx.x;
    float v = (i < n) ? fabsf(img[i]) : 0.f;
    #pragma unroll
    for (int o = 16; o > 0; o >>= 1) v = fmaxf(v, __shfl_xor_sync(0xffffffffu, v, o));
    if ((threadIdx.x & 31) == 0) atomicMax(&g_absmax_bits, __float_as_int(v));
}

__global__ void k_prepS(const float* __restrict__ cr, const float* __restrict__ ci,
                        const float* __restrict__ ph, const float* __restrict__ sg) {
    int i = blockIdx.x * blockDim.x + threadIdx.x;
    if (i < KDIM * NDIM) {
        int k = i / NDIM, t = i % NDIM;
        float val = 0.f;
        if (t < N_SW) {
            float sp, cp;
            sincosf(ph[t], &sp, &cp);
            if (k < N_SW) {
                float a = cr[k * N_SW + t], b = ci[k * N_SW + t];
                val = a * cp - b * sp;                       // C_r
            } else if (k >= KHALF && k < KHALF + N_SW) {
                int s = k - KHALF;
                float a = cr[s * N_SW + t], b = ci[s * N_SW + t];
                val = -(a * sp + b * cp);                    // -C_i
            }
        }
        g_S[i] = __float2half_rn(val);
    }
    if (i < N_SW) {
        float x = sg[i];
        g_gain[i] = fmaxf(x, 0.f) + log1pf(expf(-fabsf(x)));
    }
}

__global__ void k_pinj(const float* __restrict__ img) {
    int i = blockIdx.x * blockDim.x + threadIdx.x;
    if (i >= BATCH * NM * NV1) return;
    int b   = i / (NM * NV1);
    int rem = i - b * (NM * NV1);
    int m   = rem / NV1;
    int s   = rem - m * NV1;
    int pr = s / 7, pc = s - pr * 7;
    int ir = m >> 2, ic = m & 3;
    float am   = __int_as_float(g_absmax_bits);
    float coef = (am > 1e-8f) ? 0.3f / am : 0.3f;
    g_pinj[i] = coef * img[b * 784 + (pr * 4 + ir) * 28 + (pc * 4 + ic)];
}

// step 0: field_0 = (inject? inj*w : 0)*0.85 ; A_0 = outfun(field_0); ns<=1 edge
__global__ void k_step0(const int* __restrict__ nsp, const int* __restrict__ injp) {
    size_t i = (size_t)blockIdx.x * blockDim.x + threadIdx.x;
    if (i >= (size_t)ROWS * N_SW) return;
    const int ns = *nsp;
    int row = (int)(i / N_SW), t = (int)(i - (size_t)row * N_SW);
    int b   = row / (NLC * NM);
    int rem = row - b * (NLC * NM);
    int lc  = rem >> 4, m = rem & 15;
    float fr = 0.f;
    if (ns > 0 && *injp > 0 && t < NV1) {
        float w = 1.f - (float)lc * 0.015625f;
        fr = 0.85f * w * g_pinj[(b * NM + m) * NV1 + t];
    }
    g_fh[i] = pack_h2(fr, 0.f);
    float orr, oii;
    outfun(fr, 0.f, g_gain[t], orr, oii);
    g_A[(size_t)row * KDIM + t]         = __float2half_rn(orr);
    g_A[(size_t)row * KDIM + KHALF + t] = __float2half_rn(oii);
    if (ns <= 1 && t >= 121) {
        float e = 0.f;
        if (ns == 1) {
            float mult = (lc == 0 || lc == NLC - 1) ? 1.f : 2.f;
            e = mult * (orr * orr + oii * oii);
        }
        g_erow[(t - 121) * ROWS + row] = e;
    }
}

// ---------------- main recurrence step (steps 1..ns-1) ----------------
__global__ __launch_bounds__(TPB, 1) void k_step(int step,
                                                 const int* __restrict__ nsp,
                                                 const int* __restrict__ injp) {
    extern __shared__ unsigned char smem[];
    const int ns = *nsp;
    if (step >= ns) return;
    const int injs = *injp;
    const bool inject = (step < injs);
    const bool last   = (step == ns - 1);
    const int ktmax = (step == 1) ? 4 : 18;   // step 1: A nonzero only k<64

    {
        const uint4* ss = (const uint4*)g_S;
        uint4* ds = (uint4*)(smem + S_OFF);
        for (int i = threadIdx.x; i < S_BYTES / 16; i += TPB) ds[i] = ss[i];
    }
    const int warp = threadIdx.x >> 5;
    const int lane = threadIdx.x & 31;
    const int mtp  = warp >> 3;           // 0..2: m-tiles {2mtp, 2mtp+1}
    const int nw   = warp & 7;            // ntG = nw + 8*j

    float gain_reg[5];
    #pragma unroll
    for (int j = 0; j < 5; j++) {
        int t = lane + 32 * j;
        gain_reg[j] = (t < N_SW) ? g_gain[t] : 0.f;
    }
    __syncthreads();

    const unsigned smem_base = smem_addr(smem);

    for (int chunk = blockIdx.x; chunk < NCHUNK; chunk += GRID) {
        const int rowBase = chunk * CHUNK;

        // ---- Phase A: copy A rows (fp16, prewritten by prev step) gmem -> smem ----
        #pragma unroll
        for (int r = 0; r < 4; r++) {
            int lrow = warp * 4 + r;
            const uint4* src = (const uint4*)(g_A + (size_t)(rowBase + lrow) * KDIM);
            uint4* dst = (uint4*)(smem + A_OFF + lrow * ASTRIDE_B);
            if (lane < AG_U4) dst[lane] = src[lane];
            int i2 = lane + 32;
            if (i2 < AG_U4) dst[i2] = src[i2];
        }
        __syncthreads();   // sync1: A visible to all warps

        // ---- Phase B: 5 n-units/warp, single fp16 pass ----
        float acc[NUNIT][2][4];
        #pragma unroll
        for (int j = 0; j < NUNIT; j++)
            #pragma unroll
            for (int mi = 0; mi < 2; mi++)
                #pragma unroll
                for (int c = 0; c < 4; c++) acc[j][mi][c] = 0.f;

        for (int kt = 0; kt < ktmax; kt++) {
            unsigned aH[2][4];
            #pragma unroll
            for (int mi = 0; mi < 2; mi++) {
                unsigned arow = (lane & 15) + 16 * (2 * mtp + mi);
                unsigned acol = 16 * kt + ((lane >> 4) << 3);
                LDSM4(aH[mi], smem_base + A_OFF + arow * ASTRIDE_B + acol * 2);
            }
            const int kts2 = (kt < 9) ? kt + 9 : kt - 9;
            const bool neg = (kt < 9);
            #pragma unroll
            for (int j = 0; j < NUNIT; j++) {
                int ntG = nw + 8 * j;
                if (ntG <= 33) {
                    int G  = (ntG >= 17) ? 1 : 0;
                    int nt = ntG - 17 * G;
                    int kts = G ? kts2 : kt;
                    unsigned baddr = smem_base + (16 * kts + (lane & 15)) * SSTRIDE_B + nt * 16;
                    unsigned bh[2];
                    LDSM2T(bh, baddr);
                    if (G && neg) { bh[0] ^= 0x80008000u; bh[1] ^= 0x80008000u; }
                    MMA_F16(acc[j][0], aH[0], bh);
                    MMA_F16(acc[j][1], aH[1], bh);
                }
            }
        }

        // ---- store G fragments as packed fp16 pairs (separate buffer) ----
        {
            unsigned short* gsm16 = (unsigned short*)(smem + G_OFF);
            #pragma unroll
            for (int j = 0; j < NUNIT; j++) {
                int ntG = nw + 8 * j;
                if (ntG <= 33) {
                    int G  = (ntG >= 17) ? 1 : 0;
                    int nt = ntG - 17 * G;
                    int colBase = G * KHALF + nt * 8 + (lane & 3) * 2;
                    #pragma unroll
                    for (int mi = 0; mi < 2; mi++) {
                        int row0 = 16 * (2 * mtp + mi) + (lane >> 2);
                        float* a = acc[j][mi];
                        *(unsigned*)&gsm16[row0 * GSTR16 + colBase]       = pack_h2(a[0], a[1]);
                        *(unsigned*)&gsm16[(row0 + 8) * GSTR16 + colBase] = pack_h2(a[2], a[3]);
                    }
                }
            }
        }
        __syncthreads();   // sync2: G visible; all B-reads of A done

        // ---- Phase C: field update + produce next A; last -> energy ----
        {
            const unsigned short* gsm16 = (const unsigned short*)(smem + G_OFF);
            #pragma unroll
            for (int r = 0; r < 4; r++) {
                int lrow = warp * 4 + r;
                int grow = rowBase + lrow;
                int b    = grow / (NLC * NM);
                int rem  = grow - b * (NLC * NM);
                int lc   = rem >> 4;
                int m    = rem & 15;
                float w    = 1.0f - (float)lc * 0.015625f;
                float mult = (lc == 0 || lc == NLC - 1) ? 1.0f : 2.0f;
                unsigned* fh = g_fh + (size_t)grow * N_SW;
                __half* aout = g_A + (size_t)grow * KDIM;
                const float* pj = g_pinj + (b * NM + m) * NV1;
                #pragma unroll
                for (int j = 0; j < 5; j++) {
                    int t = lane + 32 * j;
                    if (t < N_SW) {
                        float fr, fi;
                        unpack_h2(fh[t], fr, fi);
                        if (inject && t < NV1) fr += pj[t] * w;
                        unsigned short grs = gsm16[lrow * GSTR16 + t];
                        unsigned short gis = gsm16[lrow * GSTR16 + KHALF + t];
                        float gr = __half2float(*(const __half*)&grs);
                        float gi = __half2float(*(const __half*)&gis);
                        fr = fr * 0.85f + gr * 0.25f;
                        fi = fi * 0.85f + gi * 0.25f;
                        fh[t] = pack_h2(fr, fi);
                        if (!last) {
                            float orr, oii;
                            outfun(fr, fi, gain_reg[j], orr, oii);
                            aout[t]         = __float2half_rn(orr);
                            aout[KHALF + t] = __float2half_rn(oii);
                        } else if (t >= 121) {
                            float orr, oii;
                            outfun(fr, fi, gain_reg[j], orr, oii);
                            g_erow[(t - 121) * ROWS + grow] = mult * (orr * orr + oii * oii);
                        }
                    }
                }
            }
        }
        // no trailing barrier: next sync1 orders C's G-reads before next G-store.
    }
}

// ---------------- readout ----------------
__global__ void k_final(const float* __restrict__ rw, const float* __restrict__ rb,
                        float* __restrict__ out) {
    __shared__ float feat[10];
    int b = blockIdx.x;
    int warp = threadIdx.x >> 5, lane = threadIdx.x & 31;
    if (warp < 10) {
        float s = 0.f;
        const float* e = g_erow + warp * ROWS + b * (NLC * NM);
        for (int k = lane; k < NLC * NM; k += 32) s += e[k];
        #pragma unroll
        for (int o = 16; o > 0; o >>= 1) s += __shfl_xor_sync(0xffffffffu, s, o);
        if (lane == 0) feat[warp] = log1pf(s + 1e-8f);
    }
    __syncthreads();
    if (threadIdx.x < 10) {
        int c = threadIdx.x;
        float acc = rb[c];
        #pragma unroll
        for (int o = 0; o < 10; o++) acc += feat[o] * rw[c * 10 + o];
        out[b * 10 + c] = acc;
    }
}

// ---------------- entry ----------------
extern "C" void kernel_launch(void* const* d_in, const int* in_sizes, int n_in,
                              void* d_out, int out_size) {
    const float* images = (const float*)d_in[0];
    const float* conn_r = (const float*)d_in[1];
    const float* conn_i = (const float*)d_in[2];
    const float* ph     = (const float*)d_in[3];
    const float* sg     = (const float*)d_in[4];
    const float* rw     = (const float*)d_in[5];
    const float* rb     = (const float*)d_in[6];
    const int*   nsp    = (const int*)d_in[7];
    const int*   injp   = (const int*)d_in[8];

    cudaFuncSetAttribute(k_step, cudaFuncAttributeMaxDynamicSharedMemorySize, SMEM_BYTES);

    k_init<<<1, 32>>>();
    const int n_img = BATCH * 28 * 28;
    k_absmax<<<(n_img + 511) / 512, 512>>>(images, n_img);
    k_prepS<<<(KDIM * NDIM + 255) / 256, 256>>>(conn_r, conn_i, ph, sg);
    k_pinj<<<(BATCH * NM * NV1 + 255) / 256, 256>>>(images);

    const size_t nel = (size_t)ROWS * N_SW;
    k_step0<<<(unsigned)((nel + 255) / 256), 256>>>(nsp, injp);
    for (int t = 1; t < 10; t++)
        k_step<<<GRID, TPB, SMEM_BYTES>>>(t, nsp, injp);

    k_final<<<BATCH, 320>>>(rw, rb, (float*)d_out);
}

// round 17
// speedup vs baseline: 1.1635x; 1.1635x over previous
#include <cuda_runtime.h>
#include <cuda_bf16.h>
#include <cuda_fp16.h>
#include <math.h>

// ---------------- problem constants ----------------
#define N_SW   131
#define NLC    33                 // distinct |L-32| classes
#define NM     16                 // only m<16 nonzero
#define BATCH  128
#define NV1    49
#define ROWS   (BATCH*NLC*NM)     // 67584

// ---------------- GEMM formulation ----------------
// A[row][k] fp16, k in [0,288): k<144 -> O_r (s=k), k>=144 -> O_i (s=k-144)
// S[k][t] fp16 (288 x 136): k<131 -> C_r[k][t]; 144<=k<275 -> -C_i[k-144][t]; else 0
// unit ntG in [0,34): G=ntG>=17 selects G_r/G_i, nt=ntG-17G selects n-tile.
// G_r uses S rows kt; G_i uses +-S rows kt+-9 (neg for kt<9). Single-pass fp16 MMA.
#define KHALF  144
#define KDIM   288
#define NDIM   136
#define SSTRIDE_B 272             // 17*16, ldsm-aligned
#define ASTRIDE_B 592             // 37*16, ldsm-aligned, conflict-free
#define CHUNK  96
#define NCHUNK (ROWS/CHUNK)       // 704
#define GRID   148
#define TPB    768                // 24 warps: 3 m-groups x 8 n-groups
#define NUNIT  5                  // ntG = nw + 8*j, j<5 (skip ntG>33)

#define S_BYTES  (KDIM*NDIM*2)    // 78336
#define S_OFF    0
#define A_OFF    S_BYTES          // 78336
#define A_BYTES  (CHUNK*ASTRIDE_B)// 56832
#define G_OFF    (A_OFF + A_BYTES)
#define G_BYTES  (CHUNK*ASTRIDE_B)
#define SMEM_BYTES (G_OFF + G_BYTES)   // 192000
#define GSTR16   296              // fp16 units per G row (592B, conflict-free)

// ---------------- persistent device scratch ----------------
__device__ unsigned g_fh[(size_t)ROWS * N_SW];   // field as half2 (fr,fi) - 35.4 MB
__device__ __align__(16) __half g_S[KDIM * NDIM];
__device__ float  g_gain[N_SW];
__device__ float  g_pinj[BATCH * NM * NV1];
__device__ float  g_erow[10 * ROWS];
__device__ int    g_absmax_bits;

// ---------------- helpers ----------------
__device__ __forceinline__ unsigned smem_addr(const void* p) {
    unsigned a;
    asm("{ .reg .u64 t; cvta.to.shared.u64 t, %1; cvt.u32.u64 %0, t; }" : "=r"(a) : "l"(p));
    return a;
}
#define LDSM4(R, addr) \
    asm volatile("ldmatrix.sync.aligned.m8n8.x4.shared.b16 {%0,%1,%2,%3}, [%4];" \
        : "=r"((R)[0]), "=r"((R)[1]), "=r"((R)[2]), "=r"((R)[3]) : "r"(addr))
#define LDSM2T(R, addr) \
    asm volatile("ldmatrix.sync.aligned.m8n8.x2.trans.shared.b16 {%0,%1}, [%2];" \
        : "=r"((R)[0]), "=r"((R)[1]) : "r"(addr))
#define MMA_F16(C, A, B) \
    asm volatile("mma.sync.aligned.m16n8k16.row.col.f32.f16.f16.f32 " \
        "{%0,%1,%2,%3}, {%4,%5,%6,%7}, {%8,%9}, {%0,%1,%2,%3};" \
        : "+f"((C)[0]), "+f"((C)[1]), "+f"((C)[2]), "+f"((C)[3]) \
        : "r"((A)[0]), "r"((A)[1]), "r"((A)[2]), "r"((A)[3]), "r"((B)[0]), "r"((B)[1]))

__device__ __forceinline__ float tanh_fast(float x) {
    float r;
    asm("tanh.approx.f32 %0, %1;" : "=f"(r) : "f"(x));
    return r;
}
__device__ __forceinline__ void outfun(float fr, float fi, float g,
                                       float& orr, float& oii) {
    float sq  = fmaf(fr, fr, fmaf(fi, fi, 1e-8f));
    float inv = rsqrtf(sq);
    float sc  = tanh_fast(g * sq * inv) * inv;
    orr = fr * sc;
    oii = fi * sc;
}
__device__ __forceinline__ unsigned pack_h2(float a, float b) {
    __half2 h = __floats2half2_rn(a, b);
    return *(unsigned*)&h;
}
__device__ __forceinline__ void unpack_h2(unsigned v, float& a, float& b) {
    __half2 h = *(__half2*)&v;
    float2 f = __half22float2(h);
    a = f.x; b = f.y;
}

// ---------------- prep kernels ----------------
__global__ void k_init() { if (threadIdx.x == 0) g_absmax_bits = 0; }

__global__ void k_absmax(const float* __restrict__ img, int n) {
    int i = blockIdx.x * blockDim.x + threadIdx.x;
    float v = (i < n) ? fabsf(img[i]) : 0.f;
    #pragma unroll
    for (int o = 16; o > 0; o >>= 1) v = fmaxf(v, __shfl_xor_sync(0xffffffffu, v, o));
    if ((threadIdx.x & 31) == 0) atomicMax(&g_absmax_bits, __float_as_int(v));
}

__global__ void k_prepS(const float* __restrict__ cr, const float* __restrict__ ci,
                        const float* __restrict__ ph, const float* __restrict__ sg) {
    int i = blockIdx.x * blockDim.x + threadIdx.x;
    if (i < KDIM * NDIM) {
        int k = i / NDIM, t = i % NDIM;
        float val = 0.f;
        if (t < N_SW) {
            float sp, cp;
            sincosf(ph[t], &sp, &cp);
            if (k < N_SW) {
                float a = cr[k * N_SW + t], b = ci[k * N_SW + t];
                val = a * cp - b * sp;                       // C_r
            } else if (k >= KHALF && k < KHALF + N_SW) {
                int s = k - KHALF;
                float a = cr[s * N_SW + t], b = ci[s * N_SW + t];
                val = -(a * sp + b * cp);                    // -C_i
            }
        }
        g_S[i] = __float2half_rn(val);
    }
    if (i < N_SW) {
        float x = sg[i];
        g_gain[i] = fmaxf(x, 0.f) + log1pf(expf(-fabsf(x)));
    }
}

__global__ void k_pinj(const float* __restrict__ img) {
    int i = blockIdx.x * blockDim.x + threadIdx.x;
    if (i >= BATCH * NM * NV1) return;
    int b   = i / (NM * NV1);
    int rem = i - b * (NM * NV1);
    int m   = rem / NV1;
    int s   = rem - m * NV1;
    int pr = s / 7, pc = s - pr * 7;
    int ir = m >> 2, ic = m & 3;
    float am   = __int_as_float(g_absmax_bits);
    float coef = (am > 1e-8f) ? 0.3f / am : 0.3f;
    g_pinj[i] = coef * img[b * 784 + (pr * 4 + ir) * 28 + (pc * 4 + ic)];
}

// step 0: field = (inject? inj*w : 0)*0.85, imag = 0 ; handles ns<=1 edge
__global__ void k_step0(const int* __restrict__ nsp, const int* __restrict__ injp) {
    size_t i = (size_t)blockIdx.x * blockDim.x + threadIdx.x;
    if (i >= (size_t)ROWS * N_SW) return;
    const int ns = *nsp;
    int row = (int)(i / N_SW), t = (int)(i - (size_t)row * N_SW);
    int b   = row / (NLC * NM);
    int rem = row - b * (NLC * NM);
    int lc  = rem >> 4, m = rem & 15;
    float fr = 0.f;
    if (ns > 0 && *injp > 0 && t < NV1) {
        float w = 1.f - (float)lc * 0.015625f;
        fr = 0.85f * w * g_pinj[(b * NM + m) * NV1 + t];
    }
    g_fh[i] = pack_h2(fr, 0.f);
    if (ns <= 1 && t >= 121) {
        float e = 0.f;
        if (ns == 1) {
            float orr, oii;
            outfun(fr, 0.f, g_gain[t], orr, oii);
            float mult = (lc == 0 || lc == NLC - 1) ? 1.f : 2.f;
            e = mult * (orr * orr + oii * oii);
        }
        g_erow[(t - 121) * ROWS + row] = e;
    }
}

// ---------------- main recurrence step (steps 1..ns-1) ----------------
__global__ __launch_bounds__(TPB, 1) void k_step(int step,
                                                 const int* __restrict__ nsp,
                                                 const int* __restrict__ injp) {
    extern __shared__ unsigned char smem[];
    const int ns = *nsp;
    if (step >= ns) return;
    const int injs = *injp;
    const bool inject = (step < injs);
    const bool last   = (step == ns - 1);
    const int ktmax = (step == 1) ? 4 : 18;   // step 1: A nonzero only k<64

    {
        const uint4* ss = (const uint4*)g_S;
        uint4* ds = (uint4*)(smem + S_OFF);
        for (int i = threadIdx.x; i < S_BYTES / 16; i += TPB) ds[i] = ss[i];
    }
    const int warp = threadIdx.x >> 5;
    const int lane = threadIdx.x & 31;
    const int mtp  = warp >> 3;           // 0..2: m-tiles {2mtp, 2mtp+1}
    const int nw   = warp & 7;            // ntG = nw + 8*j

    float gain_reg[5];
    #pragma unroll
    for (int j = 0; j < 5; j++) {
        int t = lane + 32 * j;
        gain_reg[j] = (t < N_SW) ? g_gain[t] : 0.f;
    }
    __syncthreads();

    const unsigned smem_base = smem_addr(smem);

    for (int chunk = blockIdx.x; chunk < NCHUNK; chunk += GRID) {
        const int rowBase = chunk * CHUNK;

        // ---- Phase A: out = f*tanh(|f|g)/|f| -> A fp16 smem (4 rows/warp) ----
        #pragma unroll
        for (int r = 0; r < 4; r++) {
            int lrow = warp * 4 + r;
            const unsigned* fh = g_fh + (size_t)(rowBase + lrow) * N_SW;
            unsigned short* ah = (unsigned short*)(smem + A_OFF + lrow * ASTRIDE_B);
            #pragma unroll
            for (int j = 0; j < 5; j++) {
                int t = lane + 32 * j;
                if (t < KHALF) {
                    float orr = 0.f, oii = 0.f;
                    if (t < N_SW) {
                        float fr, fi;
                        unpack_h2(fh[t], fr, fi);
                        outfun(fr, fi, gain_reg[j], orr, oii);
                    }
                    __half hr = __float2half_rn(orr);
                    __half hi = __float2half_rn(oii);
                    ah[t]         = *(unsigned short*)&hr;
                    ah[KHALF + t] = *(unsigned short*)&hi;
                }
            }
        }
        __syncthreads();   // sync1: A visible to all warps

        // ---- Phase B: 5 n-units/warp, single fp16 pass ----
        float acc[NUNIT][2][4];
        #pragma unroll
        for (int j = 0; j < NUNIT; j++)
            #pragma unroll
            for (int mi = 0; mi < 2; mi++)
                #pragma unroll
                for (int c = 0; c < 4; c++) acc[j][mi][c] = 0.f;

        for (int kt = 0; kt < ktmax; kt++) {
            unsigned aH[2][4];
            #pragma unroll
            for (int mi = 0; mi < 2; mi++) {
                unsigned arow = (lane & 15) + 16 * (2 * mtp + mi);
                unsigned acol = 16 * kt + ((lane >> 4) << 3);
                LDSM4(aH[mi], smem_base + A_OFF + arow * ASTRIDE_B + acol * 2);
            }
            const int kts2 = (kt < 9) ? kt + 9 : kt - 9;
            const bool neg = (kt < 9);
            #pragma unroll
            for (int j = 0; j < NUNIT; j++) {
                int ntG = nw + 8 * j;
                if (ntG <= 33) {
                    int G  = (ntG >= 17) ? 1 : 0;
                    int nt = ntG - 17 * G;
                    int kts = G ? kts2 : kt;
                    unsigned baddr = smem_base + (16 * kts + (lane & 15)) * SSTRIDE_B + nt * 16;
                    unsigned bh[2];
                    LDSM2T(bh, baddr);
                    if (G && neg) { bh[0] ^= 0x80008000u; bh[1] ^= 0x80008000u; }
                    MMA_F16(acc[j][0], aH[0], bh);
                    MMA_F16(acc[j][1], aH[1], bh);
                }
            }
        }

        // ---- store G fragments as packed fp16 pairs (separate buffer) ----
        {
            unsigned short* gsm16 = (unsigned short*)(smem + G_OFF);
            #pragma unroll
            for (int j = 0; j < NUNIT; j++) {
                int ntG = nw + 8 * j;
                if (ntG <= 33) {
                    int G  = (ntG >= 17) ? 1 : 0;
                    int nt = ntG - 17 * G;
                    int colBase = G * KHALF + nt * 8 + (lane & 3) * 2;
                    #pragma unroll
                    for (int mi = 0; mi < 2; mi++) {
                        int row0 = 16 * (2 * mtp + mi) + (lane >> 2);
                        float* a = acc[j][mi];
                        *(unsigned*)&gsm16[row0 * GSTR16 + colBase]       = pack_h2(a[0], a[1]);
                        *(unsigned*)&gsm16[(row0 + 8) * GSTR16 + colBase] = pack_h2(a[2], a[3]);
                    }
                }
            }
        }
        __syncthreads();   // sync2: G visible; all B-reads of A done

        // ---- Phase C: field update (coalesced along t); last -> energy ----
        {
            const unsigned short* gsm16 = (const unsigned short*)(smem + G_OFF);
            #pragma unroll
            for (int r = 0; r < 4; r++) {
                int lrow = warp * 4 + r;
                int grow = rowBase + lrow;
                int b    = grow / (NLC * NM);
                int rem  = grow - b * (NLC * NM);
                int lc   = rem >> 4;
                int m    = rem & 15;
                float w    = 1.0f - (float)lc * 0.015625f;
                float mult = (lc == 0 || lc == NLC - 1) ? 1.0f : 2.0f;
                unsigned* fh = g_fh + (size_t)grow * N_SW;
                const float* pj = g_pinj + (b * NM + m) * NV1;
                #pragma unroll
                for (int j = 0; j < 5; j++) {
                    int t = lane + 32 * j;
                    if (t < N_SW) {
                        float fr, fi;
                        unpack_h2(fh[t], fr, fi);
                        if (inject && t < NV1) fr += pj[t] * w;
                        unsigned short grs = gsm16[lrow * GSTR16 + t];
                        unsigned short gis = gsm16[lrow * GSTR16 + KHALF + t];
                        float gr = __half2float(*(const __half*)&grs);
                        float gi = __half2float(*(const __half*)&gis);
                        fr = fr * 0.85f + gr * 0.25f;
                        fi = fi * 0.85f + gi * 0.25f;
                        fh[t] = pack_h2(fr, fi);
                        if (last && t >= 121) {
                            float orr, oii;
                            outfun(fr, fi, gain_reg[j], orr, oii);
                            g_erow[(t - 121) * ROWS + grow] = mult * (orr * orr + oii * oii);
                        }
                    }
                }
            }
        }
        // no trailing barrier: next sync1 orders C's G-reads before next G-store.
    }
}

// ---------------- readout ----------------
__global__ void k_final(const float* __restrict__ rw, const float* __restrict__ rb,
                        float* __restrict__ out) {
    __shared__ float feat[10];
    int b = blockIdx.x;
    int warp = threadIdx.x >> 5, lane = threadIdx.x & 31;
    if (warp < 10) {
        float s = 0.f;
        const float* e = g_erow + warp * ROWS + b * (NLC * NM);
        for (int k = lane; k < NLC * NM; k += 32) s += e[k];
        #pragma unroll
        for (int o = 16; o > 0; o >>= 1) s += __shfl_xor_sync(0xffffffffu, s, o);
        if (lane == 0) feat[warp] = log1pf(s + 1e-8f);
    }
    __syncthreads();
    if (threadIdx.x < 10) {
        int c = threadIdx.x;
        float acc = rb[c];
        #pragma unroll
        for (int o = 0; o < 10; o++) acc += feat[o] * rw[c * 10 + o];
        out[b * 10 + c] = acc;
    }
}

// ---------------- entry ----------------
extern "C" void kernel_launch(void* const* d_in, const int* in_sizes, int n_in,
                              void* d_out, int out_size) {
    const float* images = (const float*)d_in[0];
    const float* conn_r = (const float*)d_in[1];
    const float* conn_i = (const float*)d_in[2];
    const float* ph     = (const float*)d_in[3];
    const float* sg     = (const float*)d_in[4];
    const float* rw     = (const float*)d_in[5];
    const float* rb     = (const float*)d_in[6];
    const int*   nsp    = (const int*)d_in[7];
    const int*   injp   = (const int*)d_in[8];

    cudaFuncSetAttribute(k_step, cudaFuncAttributeMaxDynamicSharedMemorySize, SMEM_BYTES);

    k_init<<<1, 32>>>();
    const int n_img = BATCH * 28 * 28;
    k_absmax<<<(n_img + 511) / 512, 512>>>(images, n_img);
    k_prepS<<<(KDIM * NDIM + 255) / 256, 256>>>(conn_r, conn_i, ph, sg);
    k_pinj<<<(BATCH * NM * NV1 + 255) / 256, 256>>>(images);

    const size_t nel = (size_t)ROWS * N_SW;
    k_step0<<<(unsigned)((nel + 255) / 256), 256>>>(nsp, injp);
    for (int t = 1; t < 10; t++)
        k_step<<<GRID, TPB, SMEM_BYTES>>>(t, nsp, injp);

    k_final<<<BATCH, 320>>>(rw, rb, (float*)d_out);
}